// round 14
// baseline (speedup 1.0000x reference)
#include <cuda_runtime.h>
#include <cuda_bf16.h>
#include <math.h>
#include <cstdint>

// Problem constants
#define Bn    64
#define Sn    256
#define En    256
#define Hn    256          // per-direction hidden
#define Gn    1024         // 4*Hn
#define Tn    32
#define NTOK  (Bn*Sn)      // 16384
#define KTOT  768          // 3*En  (hi/lo split GEMM K)
#define KC    32           // K per chunk (bf16)
#define NCH   (KTOT/KC)    // 24 chunks

// ---------------- scratch (static device globals; no allocation) ----------------
__device__ __align__(256) __nv_bfloat16 gA[(size_t)NTOK*KTOT];   // [m][768]
__device__ __align__(256) __nv_bfloat16 gB[(size_t)2*Gn*KTOT];   // [dir][n][768]
__device__ float g_zx[2u*NTOK*Gn];             // z[dir][t][j][g][b]  (transposed)
__device__ float g_h[2*2*Bn*Hn];               // h[parity][dir][b][j]
__device__ float g_hseq[2u*Sn*Bn*Hn];          // hseq[dir][t][b][j]  (t-major)
__device__ float g_feats[NTOK*Tn];             // feats[b][s][tag]
__device__ unsigned g_bc[2];                   // per-dir barrier counters
__device__ unsigned g_bg[2];                   // per-dir generation words (monotonic)

// ---------------- helpers -------------------------------------------------------
__device__ __forceinline__ uint32_t smem_u32(const void* p) {
    uint32_t a;
    asm("{ .reg .u64 t; cvta.to.shared.u64 t, %1; cvt.u32.u64 %0, t; }"
        : "=r"(a) : "l"(p));
    return a;
}
__device__ __forceinline__ uint32_t swz(uint32_t o) { return o ^ ((o >> 3) & 0x30); }

#define LDSM4(r, a) \
    asm volatile("ldmatrix.sync.aligned.m8n8.x4.shared.b16 {%0,%1,%2,%3}, [%4];" \
        : "=r"((r)[0]), "=r"((r)[1]), "=r"((r)[2]), "=r"((r)[3]) : "r"(a))

#define MMA16816(c, a, bv0, bv1) \
    asm volatile("mma.sync.aligned.m16n8k16.row.col.f32.bf16.bf16.f32 " \
        "{%0,%1,%2,%3}, {%4,%5,%6,%7}, {%8,%9}, {%0,%1,%2,%3};" \
        : "+f"((c)[0]), "+f"((c)[1]), "+f"((c)[2]), "+f"((c)[3]) \
        : "r"((a)[0]), "r"((a)[1]), "r"((a)[2]), "r"((a)[3]), "r"(bv0), "r"(bv1))

#define CP16(dst, src) \
    asm volatile("cp.async.cg.shared.global [%0], [%1], 16;" \
        :: "r"(dst), "l"(src) : "memory")
#define CP_COMMIT() asm volatile("cp.async.commit_group;" ::: "memory")
#define CP_WAIT(n)  asm volatile("cp.async.wait_group %0;" :: "n"(n) : "memory")

// ---------------- 1) embedding gather + hi/lo bf16 split ------------------------
__global__ void k_embed(const int* __restrict__ sent, const float* __restrict__ emb)
{
    int m = blockIdx.x;          // s*64+b
    int e = threadIdx.x;
    int b = m & 63, s = m >> 6;
    int w = sent[b * Sn + s];
    float x = emb[(size_t)w * En + e];
    __nv_bfloat16 xh = __float2bfloat16(x);
    __nv_bfloat16 xl = __float2bfloat16(x - __bfloat162float(xh));
    size_t base = (size_t)m * KTOT;
    gA[base + e]       = xh;
    gA[base + 256 + e] = xh;
    gA[base + 512 + e] = xl;
}

// ---------------- 1b) Wih hi/lo split: gB[dir][n] = [Wh | Wl | Wh] --------------
__global__ void k_wconv(const float* __restrict__ Wf, const float* __restrict__ Wb)
{
    int n   = blockIdx.x & (Gn - 1);
    int dir = blockIdx.x >> 10;
    int k   = threadIdx.x;
    const float* W = dir ? Wb : Wf;
    float w = W[(size_t)n * En + k];
    __nv_bfloat16 wh = __float2bfloat16(w);
    __nv_bfloat16 wl = __float2bfloat16(w - __bfloat162float(wh));
    size_t base = ((size_t)dir * Gn + n) * KTOT;
    gB[base + k]       = wh;
    gB[base + 256 + k] = wl;
    gB[base + 512 + k] = wh;
}

// ---------------- 2) HMMA GEMM: Zx = A·B^T + bias, transposed epilogue ----------
__global__ __launch_bounds__(256)
void k_gemm_mma(const float* __restrict__ bias_f, const float* __restrict__ bias_b)
{
    __shared__ __align__(128) __nv_bfloat16 smA[2][128 * KC];
    __shared__ __align__(128) __nv_bfloat16 smB[2][128 * KC];

    const int tid  = threadIdx.x;
    const int wid  = tid >> 5, lane = tid & 31;
    const int bm   = blockIdx.x << 7;
    const int bn   = blockIdx.y << 7;
    const int dir  = blockIdx.z;
    const int wm   = (wid & 3) << 5;
    const int wn   = (wid >> 2) << 6;

    const char* Agc = (const char*)(gA + (size_t)bm * KTOT);
    const char* Bgc = (const char*)(gB + ((size_t)dir * Gn + bn) * KTOT);

    const int lrow = tid >> 2, lc16 = tid & 3;
    const uint32_t st0 = swz((uint32_t)lrow * 64 + (lc16 << 4));
    const uint32_t st1 = swz((uint32_t)(lrow + 64) * 64 + (lc16 << 4));
    const size_t ga0 = (size_t)lrow * (KTOT * 2) + (lc16 << 4);
    const size_t ga1 = (size_t)(lrow + 64) * (KTOT * 2) + (lc16 << 4);

    const uint32_t sA0 = smem_u32(smA[0]), sA1 = smem_u32(smA[1]);
    const uint32_t sB0 = smem_u32(smB[0]), sB1 = smem_u32(smB[1]);

    uint32_t offA[2][2], offB[4][2];
#pragma unroll
    for (int mt = 0; mt < 2; mt++)
#pragma unroll
        for (int s = 0; s < 2; s++)
            offA[mt][s] = swz((uint32_t)(wm + mt * 16 + (lane & 15)) * 64
                              + s * 32 + ((lane >> 4) << 4));
#pragma unroll
    for (int p = 0; p < 4; p++)
#pragma unroll
        for (int s = 0; s < 2; s++)
            offB[p][s] = swz((uint32_t)(wn + (p << 4) + (lane & 7)
                              + ((lane >> 4) << 3)) * 64
                              + s * 32 + (((lane >> 3) & 1) << 4));

    float acc[2][8][4];
#pragma unroll
    for (int i = 0; i < 2; i++)
#pragma unroll
        for (int j = 0; j < 8; j++)
#pragma unroll
            for (int q = 0; q < 4; q++) acc[i][j][q] = 0.f;

    {
        uint4 ra0 = *(const uint4*)(Agc + ga0);
        uint4 ra1 = *(const uint4*)(Agc + ga1);
        uint4 rb0 = *(const uint4*)(Bgc + ga0);
        uint4 rb1 = *(const uint4*)(Bgc + ga1);
        *(uint4*)((char*)smA[0] + st0) = ra0;
        *(uint4*)((char*)smA[0] + st1) = ra1;
        *(uint4*)((char*)smB[0] + st0) = rb0;
        *(uint4*)((char*)smB[0] + st1) = rb1;
    }
    __syncthreads();

    for (int ch = 0; ch < NCH; ch++) {
        const int cur = ch & 1;
        const bool more = (ch + 1) < NCH;
        uint4 ra0, ra1, rb0, rb1;
        if (more) {
            size_t ko = (size_t)(ch + 1) * (KC * 2);
            ra0 = *(const uint4*)(Agc + ga0 + ko);
            ra1 = *(const uint4*)(Agc + ga1 + ko);
            rb0 = *(const uint4*)(Bgc + ga0 + ko);
            rb1 = *(const uint4*)(Bgc + ga1 + ko);
        }

        const uint32_t sA = cur ? sA1 : sA0;
        const uint32_t sB = cur ? sB1 : sB0;
#pragma unroll
        for (int s = 0; s < 2; s++) {
            uint32_t a0[4], a1[4];
            LDSM4(a0, sA + offA[0][s]);
            LDSM4(a1, sA + offA[1][s]);
#pragma unroll
            for (int p = 0; p < 4; p++) {
                uint32_t bq[4];
                LDSM4(bq, sB + offB[p][s]);
                MMA16816(acc[0][2 * p],     a0, bq[0], bq[1]);
                MMA16816(acc[0][2 * p + 1], a0, bq[2], bq[3]);
                MMA16816(acc[1][2 * p],     a1, bq[0], bq[1]);
                MMA16816(acc[1][2 * p + 1], a1, bq[2], bq[3]);
            }
        }
        __syncthreads();
        if (more) {
            char* dA = (char*)smA[cur ^ 1];
            char* dB = (char*)smB[cur ^ 1];
            *(uint4*)(dA + st0) = ra0;
            *(uint4*)(dA + st1) = ra1;
            *(uint4*)(dB + st0) = rb0;
            *(uint4*)(dB + st1) = rb1;
        }
        __syncthreads();
    }

    // transposed epilogue: z[dir][t][j][g][b]  (b-runs contiguous)
    const float* bias = dir ? bias_b : bias_f;
    const int g  = lane >> 2, tg = lane & 3;
#pragma unroll
    for (int mt = 0; mt < 2; mt++) {
        int m0  = bm + wm + mt * 16 + g;
        int t0  = m0 >> 6, b0v = m0 & 63;
        float* tbase = g_zx + (((size_t)dir * Sn + t0) << 16);
#pragma unroll
        for (int nt = 0; nt < 8; nt++) {
            int n0 = bn + wn + nt * 8 + 2 * tg;
#pragma unroll
            for (int dq = 0; dq < 2; dq++) {
                int n  = n0 + dq;
                int g2 = n >> 8, j = n & 255;
                float bv = bias[n];
                float* base = tbase + (size_t)j * 256 + g2 * 64;
                base[b0v]     = acc[mt][nt][dq]     + bv;
                base[b0v + 8] = acc[mt][nt][2 + dq] + bv;
            }
        }
    }
}

// ---------------- 3) persistent LSTM: register-blocked + cp.async 2-phase -------
// 128 blocks = (dir, 4 units). 512 thr = (bq 0..15 = warp, jj 0..3, ks 0..7).
// Thread: 4 batches x 4 gates; k split into pieces P0 [16ks,+16) and P1 [+128).
// Rows: 16 pieces x 20 floats (stride 320). Octet phases conflict-free:
// banks 20*ks mod 32 = {0,20,8,28,16,4,24,12}.
#define PROW 320
#define ZS 1040
#define SMEM_LSTM ((16*PROW + Bn*PROW + 2*ZS) * sizeof(float))

__global__ __launch_bounds__(512)
void k_lstm(const float* __restrict__ Whh_f, const float* __restrict__ Whh_b)
{
    extern __shared__ float smx[];
    float* Ws = smx;                         // [16 rows (g*4+jj)][PROW]
    float* hs = smx + 16 * PROW;             // [64 b][PROW]
    float* zs = smx + 16 * PROW + Bn * PROW; // [2][ZS]

    const int tid = threadIdx.x;
    const int dir = blockIdx.x >> 6;
    const int j0  = (blockIdx.x & 63) << 2;
    const int bq  = tid >> 5;                // warp id = batch quad
    const int jj  = (tid >> 3) & 3;
    const int ks  = tid & 7;                 // 16-k piece id (two pieces/thread)
    const int b0q = bq << 2;

    // ---- stage Whh slice: Ws[(g*4+j2)][(k>>4)*20 + (k&15)] ----
    const float* Whh = dir ? Whh_b : Whh_f;
    for (int idx = tid; idx < 4096; idx += 512) {
        int g = idx >> 10, j2 = (idx >> 8) & 3, k = idx & 255;
        Ws[(g * 4 + j2) * PROW + (k >> 4) * 20 + (k & 15)] =
            Whh[(g * Hn + j0 + j2) * Hn + k];
    }

    // zero h(parity 0) slice: 256 floats owned by this block
    if (tid < 256) {
        int b = tid >> 2, j2 = tid & 3;
        g_h[(0 * 2 + dir) * (Bn * Hn) + b * Hn + j0 + j2] = 0.f;
    }

    // first z tile into zs[0]
    {
        int t0 = dir ? (Sn - 1) : 0;
        const float* zt = g_zx + (((size_t)dir * Sn + t0) << 16) + (size_t)j0 * 256;
        int i = tid * 2;
        float2 v = *(const float2*)(zt + i);
        *(float2*)(zs + (i >> 8) * 260 + (i & 255)) = v;
    }

    // ---- hoisted cp.async staging addresses ----
    // thread stages A-chunks a = tid*4+q (k<128) and B-chunks (+32 k4).
    const int sbb  = tid >> 3;               // batch row staged
    const int sk40 = (tid & 7) << 2;         // first float4 index (k/4)
    const uint32_t dstA = smem_u32(hs) + 4u * ((uint32_t)sbb * PROW
                         + (uint32_t)(tid & 7) * 20);          // piece=tid&7, q=0
    const uint32_t dstB = dstA + 640u;       // piece += 8  (8*20 floats = 640B)
    const float* srcP0 = g_h + (0 * 2 + dir) * (Bn * Hn) + sbb * Hn + (sk40 << 2);
    const float* srcP1 = g_h + (1 * 2 + dir) * (Bn * Hn) + sbb * Hn + (sk40 << 2);

    unsigned gen = 0;
    volatile unsigned* vgen = &g_bg[dir];
    gen = *vgen;                  // monotonic across graph replays

#define GRID_BAR() do {                                                   \
        __syncthreads();                                                  \
        if (tid == 0) {                                                   \
            __threadfence();                                              \
            unsigned tgt = ++gen;                                         \
            if (atomicAdd(&g_bc[dir], 1u) == 63u) {                       \
                g_bc[dir] = 0u;                                           \
                __threadfence();                                          \
                atomicAdd(&g_bg[dir], 1u);                                \
            } else {                                                      \
                while (*vgen < tgt) { }                                   \
                __threadfence();                                          \
            }                                                             \
        }                                                                 \
        __syncthreads();                                                  \
    } while (0)

    GRID_BAR();   // h0 + first z tile visible

    float c = 0.f;                      // valid in lanes with ks<4 (b = b0q+ks)
    const float* hb0 = hs + b0q * PROW + ks * 20;        // P0 h base
    const float* wjb = Ws + jj * PROW + ks * 20;         // P0 W base (+4*PROW/gate)

    for (int st = 0; st < Sn; ++st) {
        const int t   = dir ? (Sn - 1 - st) : st;
        const int par = st & 1;

        // ---- stage h[par][dir] via cp.async: group A (k<128), group B ----
        const float* sp = par ? srcP1 : srcP0;
#pragma unroll
        for (int q = 0; q < 4; q++) CP16(dstA + 16u * q, sp + 4 * q);
        CP_COMMIT();
#pragma unroll
        for (int q = 0; q < 4; q++) CP16(dstB + 16u * q, sp + 128 + 4 * q);
        CP_COMMIT();

        // next-step z: issue LDG now; STS after compute
        float2 zv;
        int havez = (st + 1 < Sn);
        if (havez) {
            int tn2 = dir ? (Sn - 2 - st) : (st + 1);
            const float* zt = g_zx + (((size_t)dir * Sn + tn2) << 16)
                            + (size_t)j0 * 256;
            zv = *(const float2*)(zt + tid * 2);
        }

        float acc[4][4];
#pragma unroll
        for (int i = 0; i < 4; i++)
#pragma unroll
            for (int g = 0; g < 4; g++) acc[i][g] = 0.f;

        // ---- phase A ready -> compute P0 while B lands ----
        CP_WAIT(1);
        __syncthreads();
#pragma unroll
        for (int kk = 0; kk < 16; kk += 4) {
            float4 hv[4], wv[4];
#pragma unroll
            for (int i = 0; i < 4; i++)
                hv[i] = *(const float4*)(hb0 + i * PROW + kk);
#pragma unroll
            for (int g = 0; g < 4; g++)
                wv[g] = *(const float4*)(wjb + g * (4 * PROW) + kk);
#pragma unroll
            for (int i = 0; i < 4; i++)
#pragma unroll
                for (int g = 0; g < 4; g++)
                    acc[i][g] += hv[i].x * wv[g].x + hv[i].y * wv[g].y
                               + hv[i].z * wv[g].z + hv[i].w * wv[g].w;
        }

        // ---- phase B -> compute P1 (piece offset +160 floats) ----
        CP_WAIT(0);
        __syncthreads();
#pragma unroll
        for (int kk = 0; kk < 16; kk += 4) {
            float4 hv[4], wv[4];
#pragma unroll
            for (int i = 0; i < 4; i++)
                hv[i] = *(const float4*)(hb0 + i * PROW + 160 + kk);
#pragma unroll
            for (int g = 0; g < 4; g++)
                wv[g] = *(const float4*)(wjb + g * (4 * PROW) + 160 + kk);
#pragma unroll
            for (int i = 0; i < 4; i++)
#pragma unroll
                for (int g = 0; g < 4; g++)
                    acc[i][g] += hv[i].x * wv[g].x + hv[i].y * wv[g].y
                               + hv[i].z * wv[g].z + hv[i].w * wv[g].w;
        }

        // park next z tile
        if (havez) {
            int i = tid * 2;
            *(float2*)(zs + ((st + 1) & 1) * ZS + (i >> 8) * 260 + (i & 255)) = zv;
        }

        // ---- combine 8 k-pieces: xor-tree within each octet ----
#pragma unroll
        for (int m = 1; m <= 4; m <<= 1)
#pragma unroll
            for (int i = 0; i < 4; i++)
#pragma unroll
                for (int g = 0; g < 4; g++)
                    acc[i][g] += __shfl_xor_sync(0xffffffffu, acc[i][g], m);

        // ---- epilogue: lanes ks<4 each own batch b = b0q+ks ----
        if (ks < 4) {
            const float* zcur = zs + (st & 1) * ZS + jj * 260;
            int b = b0q + ks;
            float zi = zcur[0   + b] + acc[ks][0];
            float zf = zcur[64  + b] + acc[ks][1];
            float zg = zcur[128 + b] + acc[ks][2];
            float zo = zcur[192 + b] + acc[ks][3];

            float ig = 1.f / (1.f + __expf(-zi));
            float fg = 1.f / (1.f + __expf(-zf));
            float gg = 1.f - 2.f / (__expf(2.f * zg) + 1.f);
            float og = 1.f / (1.f + __expf(-zo));
            c = fg * c + ig * gg;
            float hn = og * (1.f - 2.f / (__expf(2.f * c) + 1.f));

            int j = j0 + jj;
            g_h[((par ^ 1) * 2 + dir) * (Bn * Hn) + b * Hn + j] = hn;
            g_hseq[(((size_t)dir * Sn + t) * Bn + b) * Hn + j] = hn;
        }

        GRID_BAR();
    }
#undef GRID_BAR
}

// ---------------- 4) feats = concat(h_f,h_b) @ Wout^T + bout -------------------
__global__ __launch_bounds__(256)
void k_feats(const float* __restrict__ Wout, const float* __restrict__ bout)
{
    __shared__ float Wt[128][33];

    const int tid = threadIdx.x;
    const int tag = tid & 31;
    const int ti  = tid >> 5;
    const int m   = blockIdx.x * 8 + ti;
    const int bb  = m & 63, ss = m >> 6;

    float acc = bout[tag];

    for (int cch = 0; cch < 4; cch++) {
        __syncthreads();
        for (int i = tid; i < 1024; i += 256) {
            int r = i >> 5;
            int k4 = i & 31;
            float4 w = *(const float4*)(Wout + (size_t)r * 512 + cch * 128 + (k4 << 2));
            Wt[(k4 << 2) + 0][r] = w.x;
            Wt[(k4 << 2) + 1][r] = w.y;
            Wt[(k4 << 2) + 2][r] = w.z;
            Wt[(k4 << 2) + 3][r] = w.w;
        }
        __syncthreads();

        const float* hrow;
        if (cch < 2)
            hrow = g_hseq + (((size_t)0 * Sn + ss) * Bn + bb) * Hn + cch * 128;
        else
            hrow = g_hseq + (((size_t)1 * Sn + ss) * Bn + bb) * Hn + (cch - 2) * 128;

#pragma unroll 8
        for (int k = 0; k < 128; k += 4) {
            float4 hv = *(const float4*)(hrow + k);
            acc += hv.x * Wt[k + 0][tag];
            acc += hv.y * Wt[k + 1][tag];
            acc += hv.z * Wt[k + 2][tag];
            acc += hv.w * Wt[k + 3][tag];
        }
    }
    g_feats[((size_t)(bb * Sn) + ss) * Tn + tag] = acc;
}

// ---------------- 5) Viterbi: one warp per batch, smem broadcast ---------------
__global__ void k_viterbi(const float* __restrict__ trans, float* __restrict__ out)
{
    __shared__ float vs[32];
    __shared__ unsigned char bp[Sn][32];

    const int b   = blockIdx.x;
    const int tag = threadIdx.x;

    float trc[32];
#pragma unroll
    for (int p = 0; p < 32; p++) trc[p] = trans[p * 32 + tag];

    float v = (tag == 0) ? 0.f : -10000.f;
    const float* fb = g_feats + (size_t)b * Sn * Tn;

    for (int t = 0; t < Sn; t++) {
        vs[tag] = v;
        __syncwarp();
        float best = -3.4e38f; int arg = 0;
#pragma unroll
        for (int p = 0; p < 32; p++) {
            float sc = vs[p] + trc[p];
            if (sc > best) { best = sc; arg = p; }
        }
        __syncwarp();
        bp[t][tag] = (unsigned char)arg;
        v = best + fb[t * 32 + tag];
    }

    float term = v + trc[0];
    vs[tag] = term;
    __syncwarp();
    float best = -3.4e38f; int lt = 0;
#pragma unroll
    for (int p = 0; p < 32; p++) {
        float tp = vs[p];
        if (tp > best) { best = tp; lt = p; }
    }
    __syncwarp();

    if (tag == 0) {
        int cur = lt;
        for (int t = Sn - 1; t >= 1; --t) {
            out[b * Sn + t] = (float)cur;
            cur = bp[t][cur];
        }
        out[b * Sn + 0] = (float)cur;
        out[NTOK + b]   = best;
    }
}

// ---------------- launcher -----------------------------------------------------
extern "C" void kernel_launch(void* const* d_in, const int* in_sizes, int n_in,
                              void* d_out, int out_size)
{
    const int*   sent  = (const int*)  d_in[0];
    const float* embed = (const float*)d_in[1];
    const float* Wih_f = (const float*)d_in[2];
    const float* Whh_f = (const float*)d_in[3];
    const float* b_f   = (const float*)d_in[4];
    const float* Wih_b = (const float*)d_in[5];
    const float* Whh_b = (const float*)d_in[6];
    const float* b_b   = (const float*)d_in[7];
    const float* Wout  = (const float*)d_in[8];
    const float* bout  = (const float*)d_in[9];
    const float* trans = (const float*)d_in[10];
    float* out = (float*)d_out;
    (void)in_sizes; (void)n_in; (void)out_size;

    // 1) embedding + bf16 hi/lo split of A; W split (tiny)
    k_embed<<<NTOK, 256>>>(sent, embed);
    k_wconv<<<2 * Gn, 256>>>(Wih_f, Wih_b);

    // 2) tensor-core (HMMA) input GEMM, both directions, transposed z epilogue
    dim3 gg(NTOK / 128, Gn / 128, 2);
    k_gemm_mma<<<gg, 256>>>(b_f, b_b);

    // 3) persistent recurrent kernel (register-blocked + cp.async 2-phase)
    cudaFuncSetAttribute(k_lstm, cudaFuncAttributeMaxDynamicSharedMemorySize,
                         (int)SMEM_LSTM);
    k_lstm<<<128, 512, SMEM_LSTM>>>(Whh_f, Whh_b);

    // 4) emissions
    k_feats<<<NTOK / 8, 256>>>(Wout, bout);

    // 5) viterbi decode + writeback (paths as float, then scores)
    k_viterbi<<<Bn, 32>>>(trans, out);
}

// round 15
// speedup vs baseline: 1.2445x; 1.2445x over previous
#include <cuda_runtime.h>
#include <cuda_bf16.h>
#include <math.h>
#include <cstdint>

// Problem constants
#define Bn    64
#define Sn    256
#define En    256
#define Hn    256          // per-direction hidden
#define Gn    1024         // 4*Hn
#define Tn    32
#define NTOK  (Bn*Sn)      // 16384
#define KTOT  768          // 3*En  (hi/lo split GEMM K)
#define KC    32           // K per chunk (bf16)
#define NCH   (KTOT/KC)    // 24 chunks

// ---------------- scratch (static device globals; no allocation) ----------------
__device__ __align__(256) __nv_bfloat16 gB[(size_t)2*Gn*KTOT];   // [dir][n][768]
__device__ float g_zx[2u*NTOK*Gn];             // z[dir][t][j][g][b]  (transposed)
__device__ float g_h[2*2*Bn*Hn];               // h[parity][dir][b][j]
__device__ float g_hseq[2u*Sn*Bn*Hn];          // hseq[dir][t][b][j]  (t-major)
__device__ float g_feats[NTOK*Tn];             // feats[b][s][tag]
__device__ unsigned g_bcg[2][8*32];            // group arrival counters (128B apart)
__device__ unsigned g_bcr[2*32];               // root arrival counters
__device__ unsigned g_bg[2*32];                // generation words (monotonic)

// ---------------- helpers -------------------------------------------------------
__device__ __forceinline__ uint32_t smem_u32(const void* p) {
    uint32_t a;
    asm("{ .reg .u64 t; cvta.to.shared.u64 t, %1; cvt.u32.u64 %0, t; }"
        : "=r"(a) : "l"(p));
    return a;
}
__device__ __forceinline__ uint32_t swz(uint32_t o) { return o ^ ((o >> 3) & 0x30); }

#define LDSM4(r, a) \
    asm volatile("ldmatrix.sync.aligned.m8n8.x4.shared.b16 {%0,%1,%2,%3}, [%4];" \
        : "=r"((r)[0]), "=r"((r)[1]), "=r"((r)[2]), "=r"((r)[3]) : "r"(a))

#define MMA16816(c, a, bv0, bv1) \
    asm volatile("mma.sync.aligned.m16n8k16.row.col.f32.bf16.bf16.f32 " \
        "{%0,%1,%2,%3}, {%4,%5,%6,%7}, {%8,%9}, {%0,%1,%2,%3};" \
        : "+f"((c)[0]), "+f"((c)[1]), "+f"((c)[2]), "+f"((c)[3]) \
        : "r"((a)[0]), "r"((a)[1]), "r"((a)[2]), "r"((a)[3]), "r"(bv0), "r"(bv1))

// gather 8 bf16 (16B) of the [xh|xh|xl] expansion directly from an embed row
__device__ __forceinline__ uint4 gather_bf16x8(const float* ebrow, int kk)
{
    int col = kk & 255;
    float4 f0 = *(const float4*)(ebrow + col);
    float4 f1 = *(const float4*)(ebrow + col + 4);
    uint4 r;
    if (kk < 512) {                   // hi terms (uniform per chunk, no divergence)
        __nv_bfloat162 p0 = __floats2bfloat162_rn(f0.x, f0.y);
        __nv_bfloat162 p1 = __floats2bfloat162_rn(f0.z, f0.w);
        __nv_bfloat162 p2 = __floats2bfloat162_rn(f1.x, f1.y);
        __nv_bfloat162 p3 = __floats2bfloat162_rn(f1.z, f1.w);
        r.x = *(uint32_t*)&p0; r.y = *(uint32_t*)&p1;
        r.z = *(uint32_t*)&p2; r.w = *(uint32_t*)&p3;
    } else {                          // lo residual terms
        float a[8] = {f0.x, f0.y, f0.z, f0.w, f1.x, f1.y, f1.z, f1.w};
        uint32_t q[4];
#pragma unroll
        for (int i = 0; i < 4; i++) {
            float x0 = a[2 * i], x1 = a[2 * i + 1];
            float l0 = x0 - __bfloat162float(__float2bfloat16(x0));
            float l1 = x1 - __bfloat162float(__float2bfloat16(x1));
            __nv_bfloat162 p = __floats2bfloat162_rn(l0, l1);
            q[i] = *(uint32_t*)&p;
        }
        r.x = q[0]; r.y = q[1]; r.z = q[2]; r.w = q[3];
    }
    return r;
}

// ---------------- 1) Wih hi/lo split: gB[dir][n] = [Wh | Wl | Wh] ---------------
__global__ void k_wconv(const float* __restrict__ Wf, const float* __restrict__ Wb)
{
    int n   = blockIdx.x & (Gn - 1);
    int dir = blockIdx.x >> 10;
    int k   = threadIdx.x;
    const float* W = dir ? Wb : Wf;
    float w = W[(size_t)n * En + k];
    __nv_bfloat16 wh = __float2bfloat16(w);
    __nv_bfloat16 wl = __float2bfloat16(w - __bfloat162float(wh));
    size_t base = ((size_t)dir * Gn + n) * KTOT;
    gB[base + k]       = wh;
    gB[base + 256 + k] = wl;
    gB[base + 512 + k] = wh;
}

// ---------------- 2) HMMA GEMM: Zx = x·Wih^T + bias, fused embed gather ---------
__global__ __launch_bounds__(256)
void k_gemm_mma(const float* __restrict__ bias_f, const float* __restrict__ bias_b,
                const int* __restrict__ sent, const float* __restrict__ emb)
{
    __shared__ __align__(128) __nv_bfloat16 smA[2][128 * KC];
    __shared__ __align__(128) __nv_bfloat16 smB[2][128 * KC];

    const int tid  = threadIdx.x;
    const int wid  = tid >> 5, lane = tid & 31;
    const int bm   = blockIdx.x << 7;
    const int bn   = blockIdx.y << 7;
    const int dir  = blockIdx.z;
    const int wm   = (wid & 3) << 5;
    const int wn   = (wid >> 2) << 6;

    const char* Bgc = (const char*)(gB + ((size_t)dir * Gn + bn) * KTOT);

    const int lrow = tid >> 2, lc16 = tid & 3;
    const uint32_t st0 = swz((uint32_t)lrow * 64 + (lc16 << 4));
    const uint32_t st1 = swz((uint32_t)(lrow + 64) * 64 + (lc16 << 4));
    const size_t gb0 = (size_t)lrow * (KTOT * 2) + (lc16 << 4);
    const size_t gb1 = (size_t)(lrow + 64) * (KTOT * 2) + (lc16 << 4);

    // embed rows for this loader thread's two A rows (hoisted)
    const int m0 = bm + lrow, m1 = bm + lrow + 64;
    const float* eb0 = emb + (size_t)sent[(m0 & 63) * Sn + (m0 >> 6)] * En;
    const float* eb1 = emb + (size_t)sent[(m1 & 63) * Sn + (m1 >> 6)] * En;
    const int kbase = lc16 << 3;      // 8 bf16 per 16B chunk

    const uint32_t sA0 = smem_u32(smA[0]), sA1 = smem_u32(smA[1]);
    const uint32_t sB0 = smem_u32(smB[0]), sB1 = smem_u32(smB[1]);

    uint32_t offA[2][2], offB[4][2];
#pragma unroll
    for (int mt = 0; mt < 2; mt++)
#pragma unroll
        for (int s = 0; s < 2; s++)
            offA[mt][s] = swz((uint32_t)(wm + mt * 16 + (lane & 15)) * 64
                              + s * 32 + ((lane >> 4) << 4));
#pragma unroll
    for (int p = 0; p < 4; p++)
#pragma unroll
        for (int s = 0; s < 2; s++)
            offB[p][s] = swz((uint32_t)(wn + (p << 4) + (lane & 7)
                              + ((lane >> 4) << 3)) * 64
                              + s * 32 + (((lane >> 3) & 1) << 4));

    float acc[2][8][4];
#pragma unroll
    for (int i = 0; i < 2; i++)
#pragma unroll
        for (int j = 0; j < 8; j++)
#pragma unroll
            for (int q = 0; q < 4; q++) acc[i][j][q] = 0.f;

    {
        uint4 ra0 = gather_bf16x8(eb0, kbase);
        uint4 ra1 = gather_bf16x8(eb1, kbase);
        uint4 rb0 = *(const uint4*)(Bgc + gb0);
        uint4 rb1 = *(const uint4*)(Bgc + gb1);
        *(uint4*)((char*)smA[0] + st0) = ra0;
        *(uint4*)((char*)smA[0] + st1) = ra1;
        *(uint4*)((char*)smB[0] + st0) = rb0;
        *(uint4*)((char*)smB[0] + st1) = rb1;
    }
    __syncthreads();

    for (int ch = 0; ch < NCH; ch++) {
        const int cur = ch & 1;
        const bool more = (ch + 1) < NCH;
        uint4 ra0, ra1, rb0, rb1;
        if (more) {
            int kk = (ch + 1) * KC + kbase;
            size_t ko = (size_t)(ch + 1) * (KC * 2);
            ra0 = gather_bf16x8(eb0, kk);
            ra1 = gather_bf16x8(eb1, kk);
            rb0 = *(const uint4*)(Bgc + gb0 + ko);
            rb1 = *(const uint4*)(Bgc + gb1 + ko);
        }

        const uint32_t sA = cur ? sA1 : sA0;
        const uint32_t sB = cur ? sB1 : sB0;
#pragma unroll
        for (int s = 0; s < 2; s++) {
            uint32_t a0[4], a1[4];
            LDSM4(a0, sA + offA[0][s]);
            LDSM4(a1, sA + offA[1][s]);
#pragma unroll
            for (int p = 0; p < 4; p++) {
                uint32_t bq[4];
                LDSM4(bq, sB + offB[p][s]);
                MMA16816(acc[0][2 * p],     a0, bq[0], bq[1]);
                MMA16816(acc[0][2 * p + 1], a0, bq[2], bq[3]);
                MMA16816(acc[1][2 * p],     a1, bq[0], bq[1]);
                MMA16816(acc[1][2 * p + 1], a1, bq[2], bq[3]);
            }
        }
        __syncthreads();
        if (more) {
            char* dA = (char*)smA[cur ^ 1];
            char* dB = (char*)smB[cur ^ 1];
            *(uint4*)(dA + st0) = ra0;
            *(uint4*)(dA + st1) = ra1;
            *(uint4*)(dB + st0) = rb0;
            *(uint4*)(dB + st1) = rb1;
        }
        __syncthreads();
    }

    // transposed epilogue: z[dir][t][j][g][b]  (b-runs contiguous)
    const float* bias = dir ? bias_b : bias_f;
    const int g  = lane >> 2, tg = lane & 3;
#pragma unroll
    for (int mt = 0; mt < 2; mt++) {
        int mm  = bm + wm + mt * 16 + g;
        int t0  = mm >> 6, b0v = mm & 63;
        float* tbase = g_zx + (((size_t)dir * Sn + t0) << 16);
#pragma unroll
        for (int nt = 0; nt < 8; nt++) {
            int n0 = bn + wn + nt * 8 + 2 * tg;
#pragma unroll
            for (int dq = 0; dq < 2; dq++) {
                int n  = n0 + dq;
                int g2 = n >> 8, j = n & 255;
                float bv = bias[n];
                float* base = tbase + (size_t)j * 256 + g2 * 64;
                base[b0v]     = acc[mt][nt][dq]     + bv;
                base[b0v + 8] = acc[mt][nt][2 + dq] + bv;
            }
        }
    }
}

// ---------------- 3) persistent LSTM: register-blocked 4b x 4g tiles ------------
// 128 blocks = (dir, 4 hidden units). 512 thr = (bq 0..15 = warp, jj 0..3, ks 0..7).
// Barrier: 2-level arrival tree (8 groups of 8, separate lines) + root release.
#define WROW 288           // 8 segs x 36
#define ZS 1040
#define SMEM_LSTM ((16*WROW + Bn*WROW + 2*ZS) * sizeof(float))

__global__ __launch_bounds__(512)
void k_lstm(const float* __restrict__ Whh_f, const float* __restrict__ Whh_b)
{
    extern __shared__ float smx[];
    float* Ws = smx;                         // [16 rows (g*4+jj)][WROW]
    float* hs = smx + 16 * WROW;             // [64 b][WROW]
    float* zs = smx + 16 * WROW + Bn * WROW; // [2][ZS]

    const int tid = threadIdx.x;
    const int dir = blockIdx.x >> 6;
    const int blk = blockIdx.x & 63;
    const int j0  = blk << 2;
    const int bq  = tid >> 5;                // warp id = batch quad
    const int jj  = (tid >> 3) & 3;
    const int ks  = tid & 7;                 // k segment (32 k each)
    const int b0q = bq << 2;

    // ---- stage Whh slice: Ws[(g*4+j2)][ks2*36 + kk] ----
    const float* Whh = dir ? Whh_b : Whh_f;
    for (int idx = tid; idx < 4096; idx += 512) {
        int g = idx >> 10, j2 = (idx >> 8) & 3, k = idx & 255;
        Ws[(g * 4 + j2) * WROW + (k >> 5) * 36 + (k & 31)] =
            Whh[(g * Hn + j0 + j2) * Hn + k];
    }

    // zero h(parity 0) slice: 256 floats owned by this block
    if (tid < 256) {
        int b = tid >> 2, j2 = tid & 3;
        g_h[(0 * 2 + dir) * (Bn * Hn) + b * Hn + j0 + j2] = 0.f;
    }

    // first z tile into zs[0]
    {
        int t0 = dir ? (Sn - 1) : 0;
        const float* zt = g_zx + (((size_t)dir * Sn + t0) << 16) + (size_t)j0 * 256;
        int i = tid * 2;
        float2 v = *(const float2*)(zt + i);
        *(float2*)(zs + (i >> 8) * 260 + (i & 255)) = v;
    }

    volatile unsigned* vgen = &g_bg[dir * 32];
    unsigned gen = *vgen;                  // monotonic across graph replays
    const int grp = blk >> 3;

#define GRID_BAR() do {                                                        \
        __syncthreads();                                                       \
        if (tid == 0) {                                                        \
            __threadfence();                                                   \
            unsigned tgt = ++gen;                                              \
            bool released = false;                                             \
            if (atomicAdd(&g_bcg[dir][grp * 32], 1u) == 8u * tgt - 1u) {       \
                if (atomicAdd(&g_bcr[dir * 32], 1u) == 8u * tgt - 1u) {        \
                    __threadfence();                                           \
                    atomicAdd(&g_bg[dir * 32], 1u);                            \
                    released = true;                                           \
                }                                                              \
            }                                                                  \
            if (!released) { while (*vgen < tgt) { } }                         \
            __threadfence();                                                   \
        }                                                                      \
        __syncthreads();                                                       \
    } while (0)

    GRID_BAR();   // h0 + first z tile visible

    float c = 0.f;                      // valid in lanes with ks<4 (b = b0q+ks)
    const float* hb = hs + b0q * WROW + ks * 36;
    const float* wj = Ws + jj * WROW + ks * 36;   // + g*4*WROW per gate

    for (int st = 0; st < Sn; ++st) {
        const int t   = dir ? (Sn - 1 - st) : st;
        const int par = st & 1;

        // ---- stage h[par][dir] (64KB) into segmented layout ----
        const float4* hp = (const float4*)(g_h + (par * 2 + dir) * (Bn * Hn));
#pragma unroll
        for (int i = 0; i < 8; i++) {
            int li = tid + (i << 9);
            float4 v = hp[li];
            int bb = li >> 6, k4 = li & 63;
            *(float4*)(hs + bb * WROW + (k4 >> 3) * 36 + ((k4 & 7) << 2)) = v;
        }
        __syncthreads();

        // ---- register-blocked 4b x 4g over this thread's 32-k segment ----
        float acc[4][4];
#pragma unroll
        for (int i = 0; i < 4; i++)
#pragma unroll
            for (int g = 0; g < 4; g++) acc[i][g] = 0.f;

#pragma unroll
        for (int kk = 0; kk < 32; kk += 4) {
            float4 hv[4], wv[4];
#pragma unroll
            for (int i = 0; i < 4; i++)
                hv[i] = *(const float4*)(hb + i * WROW + kk);
#pragma unroll
            for (int g = 0; g < 4; g++)
                wv[g] = *(const float4*)(wj + g * (4 * WROW) + kk);
#pragma unroll
            for (int i = 0; i < 4; i++)
#pragma unroll
                for (int g = 0; g < 4; g++)
                    acc[i][g] += hv[i].x * wv[g].x + hv[i].y * wv[g].y
                               + hv[i].z * wv[g].z + hv[i].w * wv[g].w;
        }

        // prefetch next z tile (hides under combine+epilogue+barrier)
        if (st + 1 < Sn) {
            int tn2 = dir ? (Sn - 2 - st) : (st + 1);
            const float* zt = g_zx + (((size_t)dir * Sn + tn2) << 16)
                            + (size_t)j0 * 256;
            int i = tid * 2;
            float2 v = *(const float2*)(zt + i);
            *(float2*)(zs + ((st + 1) & 1) * ZS + (i >> 8) * 260 + (i & 255)) = v;
        }

        // ---- combine 8 k-segments: xor-tree within each octet ----
#pragma unroll
        for (int m = 1; m <= 4; m <<= 1)
#pragma unroll
            for (int i = 0; i < 4; i++)
#pragma unroll
                for (int g = 0; g < 4; g++)
                    acc[i][g] += __shfl_xor_sync(0xffffffffu, acc[i][g], m);

        // ---- epilogue: lanes ks<4 each own batch b = b0q+ks ----
        if (ks < 4) {
            const float* zcur = zs + (st & 1) * ZS + jj * 260;
            int b = b0q + ks;
            float zi = zcur[0   + b] + acc[ks][0];
            float zf = zcur[64  + b] + acc[ks][1];
            float zg = zcur[128 + b] + acc[ks][2];
            float zo = zcur[192 + b] + acc[ks][3];

            float ig = 1.f / (1.f + __expf(-zi));
            float fg = 1.f / (1.f + __expf(-zf));
            float gg = 1.f - 2.f / (__expf(2.f * zg) + 1.f);
            float og = 1.f / (1.f + __expf(-zo));
            c = fg * c + ig * gg;
            float hn = og * (1.f - 2.f / (__expf(2.f * c) + 1.f));

            int j = j0 + jj;
            g_h[((par ^ 1) * 2 + dir) * (Bn * Hn) + b * Hn + j] = hn;
            g_hseq[(((size_t)dir * Sn + t) * Bn + b) * Hn + j] = hn;
        }

        GRID_BAR();
    }
#undef GRID_BAR
}

// ---------------- 4) feats = concat(h_f,h_b) @ Wout^T + bout -------------------
__global__ __launch_bounds__(256)
void k_feats(const float* __restrict__ Wout, const float* __restrict__ bout)
{
    __shared__ float Wt[128][33];

    const int tid = threadIdx.x;
    const int tag = tid & 31;
    const int ti  = tid >> 5;
    const int m   = blockIdx.x * 8 + ti;
    const int bb  = m & 63, ss = m >> 6;

    float acc = bout[tag];

    for (int cch = 0; cch < 4; cch++) {
        __syncthreads();
        for (int i = tid; i < 1024; i += 256) {
            int r = i >> 5;
            int k4 = i & 31;
            float4 w = *(const float4*)(Wout + (size_t)r * 512 + cch * 128 + (k4 << 2));
            Wt[(k4 << 2) + 0][r] = w.x;
            Wt[(k4 << 2) + 1][r] = w.y;
            Wt[(k4 << 2) + 2][r] = w.z;
            Wt[(k4 << 2) + 3][r] = w.w;
        }
        __syncthreads();

        const float* hrow;
        if (cch < 2)
            hrow = g_hseq + (((size_t)0 * Sn + ss) * Bn + bb) * Hn + cch * 128;
        else
            hrow = g_hseq + (((size_t)1 * Sn + ss) * Bn + bb) * Hn + (cch - 2) * 128;

#pragma unroll 8
        for (int k = 0; k < 128; k += 4) {
            float4 hv = *(const float4*)(hrow + k);
            acc += hv.x * Wt[k + 0][tag];
            acc += hv.y * Wt[k + 1][tag];
            acc += hv.z * Wt[k + 2][tag];
            acc += hv.w * Wt[k + 3][tag];
        }
    }
    g_feats[((size_t)(bb * Sn) + ss) * Tn + tag] = acc;
}

// ---------------- 5) Viterbi: one warp per batch, smem broadcast ---------------
__global__ void k_viterbi(const float* __restrict__ trans, float* __restrict__ out)
{
    __shared__ float vs[32];
    __shared__ unsigned char bp[Sn][32];

    const int b   = blockIdx.x;
    const int tag = threadIdx.x;

    float trc[32];
#pragma unroll
    for (int p = 0; p < 32; p++) trc[p] = trans[p * 32 + tag];

    float v = (tag == 0) ? 0.f : -10000.f;
    const float* fb = g_feats + (size_t)b * Sn * Tn;

    for (int t = 0; t < Sn; t++) {
        vs[tag] = v;
        __syncwarp();
        float best = -3.4e38f; int arg = 0;
#pragma unroll
        for (int p = 0; p < 32; p++) {
            float sc = vs[p] + trc[p];
            if (sc > best) { best = sc; arg = p; }
        }
        __syncwarp();
        bp[t][tag] = (unsigned char)arg;
        v = best + fb[t * 32 + tag];
    }

    float term = v + trc[0];
    vs[tag] = term;
    __syncwarp();
    float best = -3.4e38f; int lt = 0;
#pragma unroll
    for (int p = 0; p < 32; p++) {
        float tp = vs[p];
        if (tp > best) { best = tp; lt = p; }
    }
    __syncwarp();

    if (tag == 0) {
        int cur = lt;
        for (int t = Sn - 1; t >= 1; --t) {
            out[b * Sn + t] = (float)cur;
            cur = bp[t][cur];
        }
        out[b * Sn + 0] = (float)cur;
        out[NTOK + b]   = best;
    }
}

// ---------------- launcher -----------------------------------------------------
extern "C" void kernel_launch(void* const* d_in, const int* in_sizes, int n_in,
                              void* d_out, int out_size)
{
    const int*   sent  = (const int*)  d_in[0];
    const float* embed = (const float*)d_in[1];
    const float* Wih_f = (const float*)d_in[2];
    const float* Whh_f = (const float*)d_in[3];
    const float* b_f   = (const float*)d_in[4];
    const float* Wih_b = (const float*)d_in[5];
    const float* Whh_b = (const float*)d_in[6];
    const float* b_b   = (const float*)d_in[7];
    const float* Wout  = (const float*)d_in[8];
    const float* bout  = (const float*)d_in[9];
    const float* trans = (const float*)d_in[10];
    float* out = (float*)d_out;
    (void)in_sizes; (void)n_in; (void)out_size;

    // 1) Wih hi/lo split (tiny); embedding gather is fused into the GEMM
    k_wconv<<<2 * Gn, 256>>>(Wih_f, Wih_b);

    // 2) tensor-core (HMMA) input GEMM with fused embed gather, both directions
    dim3 gg(NTOK / 128, Gn / 128, 2);
    k_gemm_mma<<<gg, 256>>>(b_f, b_b, sent, embed);

    // 3) persistent recurrent kernel (register-blocked, tree barrier)
    cudaFuncSetAttribute(k_lstm, cudaFuncAttributeMaxDynamicSharedMemorySize,
                         (int)SMEM_LSTM);
    k_lstm<<<128, 512, SMEM_LSTM>>>(Whh_f, Whh_b);

    // 4) emissions
    k_feats<<<NTOK / 8, 256>>>(Wout, bout);

    // 5) viterbi decode + writeback (paths as float, then scores)
    k_viterbi<<<Bn, 32>>>(trans, out);
}